// round 2
// baseline (speedup 1.0000x reference)
#include <cuda_runtime.h>

#define N_NODES 100000
#define N_EDGES 1000000
#define D 64
#define NCHUNK (D / 4)   // float4 chunks per node row = 16

// -------- scratch (device globals; no allocation anywhere) --------
__device__ int    g_deg_out[N_NODES];
__device__ int    g_deg_in[N_NODES];
__device__ float  g_norm_out[N_NODES];
__device__ float  g_norm_in[N_NODES];
__device__ float4 g_agg[N_NODES * NCHUNK];   // aggregation buffer [N, 64]
__device__ float4 g_h[N_NODES * NCHUNK];     // hidden layer [N, 64]

// -------- one-time graph preprocessing (recomputed every replay) --------
__global__ void k_zero_deg() {
    int i = blockIdx.x * blockDim.x + threadIdx.x;
    if (i < N_NODES) { g_deg_out[i] = 0; g_deg_in[i] = 0; }
}

__global__ void k_hist(const int* __restrict__ src, const int* __restrict__ dst) {
    int i = blockIdx.x * blockDim.x + threadIdx.x;
    if (i < N_EDGES) {
        atomicAdd(&g_deg_out[src[i]], 1);
        atomicAdd(&g_deg_in[dst[i]], 1);
    }
}

__global__ void k_norms() {
    int i = blockIdx.x * blockDim.x + threadIdx.x;
    if (i < N_NODES) {
        g_norm_out[i] = rsqrtf((float)max(g_deg_out[i], 1));
        g_norm_in[i]  = rsqrtf((float)max(g_deg_in[i], 1));
    }
}

__global__ void k_zero_agg() {
    int i = blockIdx.x * blockDim.x + threadIdx.x;
    if (i < N_NODES * NCHUNK) g_agg[i] = make_float4(0.f, 0.f, 0.f, 0.f);
}

// -------- edge scatter: agg[dst] += norm_out[src] * xin[src] --------
// 16 threads per edge, one float4 chunk each. Feature gathers are coalesced
// (16 consecutive threads read one node's 256B row). red.global.add.v4.f32
// is a no-return vector reduction (1 instr per 16B instead of 4 atomics).
// xin == nullptr -> read from internal g_h (layer 2).
__global__ void k_scatter(const int* __restrict__ src, const int* __restrict__ dst,
                          const float4* __restrict__ xin) {
    const float4* __restrict__ x = xin ? xin : (const float4*)g_h;
    int i = blockIdx.x * blockDim.x + threadIdx.x;
    if (i >= N_EDGES * NCHUNK) return;
    int e = i >> 4;
    int c = i & 15;
    int s = __ldg(src + e);
    int d = __ldg(dst + e);
    float no = __ldg(g_norm_out + s);
    float4 v = __ldg(x + s * NCHUNK + c);
    v.x *= no; v.y *= no; v.z *= no; v.w *= no;
    float4* p = g_agg + (size_t)d * NCHUNK + c;
    asm volatile("red.global.add.v4.f32 [%0], {%1, %2, %3, %4};"
                 :: "l"(p), "f"(v.x), "f"(v.y), "f"(v.z), "f"(v.w)
                 : "memory");
}

// -------- fused: out = act( (g_agg * norm_in[v]) @ W + b ) --------
// One warp per node. Each lane owns output columns {lane, lane+32}.
// W (16KB) staged in shared; a[k] broadcast via shfl from two coalesced loads.
// outp == nullptr -> write to internal g_h (layer 1, with relu).
__global__ void __launch_bounds__(256) k_gemm(const float* __restrict__ W,
                                              const float* __restrict__ b,
                                              float* outp,
                                              int relu) {
    float* __restrict__ out = outp ? outp : (float*)g_h;
    const float* __restrict__ in = (const float*)g_agg;
    __shared__ float Ws[D * D];
    for (int i = threadIdx.x; i < D * D; i += blockDim.x) Ws[i] = W[i];
    __syncthreads();

    int lane = threadIdx.x & 31;
    int warp = threadIdx.x >> 5;
    int wpb  = blockDim.x >> 5;
    float b0 = __ldg(b + lane);
    float b1 = __ldg(b + 32 + lane);

    for (int v = blockIdx.x * wpb + warp; v < N_NODES; v += gridDim.x * wpb) {
        float ni = __ldg(g_norm_in + v);
        float a0 = in[(size_t)v * D + lane] * ni;
        float a1 = in[(size_t)v * D + 32 + lane] * ni;
        float acc0 = b0, acc1 = b1;
#pragma unroll
        for (int k = 0; k < 32; k++) {
            float ak = __shfl_sync(0xffffffffu, a0, k);
            acc0 = fmaf(ak, Ws[k * D + lane], acc0);
            acc1 = fmaf(ak, Ws[k * D + 32 + lane], acc1);
        }
#pragma unroll
        for (int k = 0; k < 32; k++) {
            float ak = __shfl_sync(0xffffffffu, a1, k);
            acc0 = fmaf(ak, Ws[(k + 32) * D + lane], acc0);
            acc1 = fmaf(ak, Ws[(k + 32) * D + 32 + lane], acc1);
        }
        if (relu) { acc0 = fmaxf(acc0, 0.f); acc1 = fmaxf(acc1, 0.f); }
        out[(size_t)v * D + lane] = acc0;
        out[(size_t)v * D + 32 + lane] = acc1;
    }
}

extern "C" void kernel_launch(void* const* d_in, const int* in_sizes, int n_in,
                              void* d_out, int out_size) {
    const int*   src = (const int*)d_in[0];
    const int*   dst = (const int*)d_in[1];
    const float* x   = (const float*)d_in[2];
    const float* W1  = (const float*)d_in[3];
    const float* b1  = (const float*)d_in[4];
    const float* W2  = (const float*)d_in[5];
    const float* b2  = (const float*)d_in[6];
    float* out = (float*)d_out;

    const int T = 256;
    // graph preprocessing (deterministic, recomputed each call)
    k_zero_deg<<<(N_NODES + T - 1) / T, T>>>();
    k_hist<<<(N_EDGES + T - 1) / T, T>>>(src, dst);
    k_norms<<<(N_NODES + T - 1) / T, T>>>();

    const int scatter_blocks = (N_EDGES * NCHUNK + T - 1) / T;
    const int zero_blocks    = (N_NODES * NCHUNK + T - 1) / T;

    // ---- layer 1: agg = scatter(x); h = relu(agg*norm_in @ W1 + b1) ----
    k_zero_agg<<<zero_blocks, T>>>();
    k_scatter<<<scatter_blocks, T>>>(src, dst, (const float4*)x);
    k_gemm<<<2048, T>>>(W1, b1, nullptr, 1);

    // ---- layer 2: agg = scatter(h); out = agg*norm_in @ W2 + b2 ----
    k_zero_agg<<<zero_blocks, T>>>();
    k_scatter<<<scatter_blocks, T>>>(src, dst, nullptr);
    k_gemm<<<2048, T>>>(W2, b2, out, 0);
}

// round 4
// speedup vs baseline: 1.1537x; 1.1537x over previous
#include <cuda_runtime.h>

#define N_NODES 100000
#define N_EDGES 1000000
#define D 64
#define SCAN_BS 1024
#define SCAN_NB ((N_NODES + SCAN_BS - 1) / SCAN_BS)   // 98

// -------- scratch (device globals; no allocation anywhere) --------
__device__ int   g_deg_out[N_NODES];
__device__ int   g_deg_in[N_NODES];
__device__ float g_norm_out[N_NODES];
__device__ float g_norm_in[N_NODES];
__device__ int   g_rowptr[N_NODES + 1];   // CSR by dst
__device__ int   g_fill[N_NODES];         // bucket cursors
__device__ int   g_esrc[N_EDGES];         // src ids grouped by dst
__device__ int   g_bsum[SCAN_NB];
__device__ int   g_boff[SCAN_NB];
__device__ float g_h[N_NODES * D];        // hidden layer

// ============ graph preprocessing (recomputed every replay) ============
__global__ void k_zero_deg() {
    int i = blockIdx.x * blockDim.x + threadIdx.x;
    if (i < N_NODES) { g_deg_out[i] = 0; g_deg_in[i] = 0; }
}

__global__ void k_hist(const int* __restrict__ src, const int* __restrict__ dst) {
    int i = blockIdx.x * blockDim.x + threadIdx.x;
    if (i < N_EDGES) {
        atomicAdd(&g_deg_out[src[i]], 1);
        atomicAdd(&g_deg_in[dst[i]], 1);
    }
}

__global__ void k_norms() {
    int i = blockIdx.x * blockDim.x + threadIdx.x;
    if (i < N_NODES) {
        g_norm_out[i] = rsqrtf((float)max(g_deg_out[i], 1));
        g_norm_in[i]  = rsqrtf((float)max(g_deg_in[i], 1));
    }
}

// exclusive scan of deg_in -> rowptr, 3 passes
__global__ void k_scan1() {
    __shared__ int s[SCAN_BS];
    int t = threadIdx.x;
    int i = blockIdx.x * SCAN_BS + t;
    int v = (i < N_NODES) ? g_deg_in[i] : 0;
    s[t] = v;
    __syncthreads();
    for (int o = 1; o < SCAN_BS; o <<= 1) {
        int u = (t >= o) ? s[t - o] : 0;
        __syncthreads();
        s[t] += u;
        __syncthreads();
    }
    if (i < N_NODES) g_rowptr[i] = s[t] - v;     // exclusive within block
    if (t == SCAN_BS - 1) g_bsum[blockIdx.x] = s[t];
}

__global__ void k_scan2() {   // single block, 128 threads, scans 98 sums
    __shared__ int s[128];
    int t = threadIdx.x;
    int v = (t < SCAN_NB) ? g_bsum[t] : 0;
    s[t] = v;
    __syncthreads();
    for (int o = 1; o < 128; o <<= 1) {
        int u = (t >= o) ? s[t - o] : 0;
        __syncthreads();
        s[t] += u;
        __syncthreads();
    }
    if (t < SCAN_NB) g_boff[t] = s[t] - v;       // exclusive
}

__global__ void k_scan3() {
    int i = blockIdx.x * blockDim.x + threadIdx.x;
    if (i < N_NODES) {
        int r = g_rowptr[i] + g_boff[i >> 10];
        g_rowptr[i] = r;
        g_fill[i] = r;
    }
    if (i == 0) g_rowptr[N_NODES] = N_EDGES;
}

__global__ void k_bucket(const int* __restrict__ src, const int* __restrict__ dst) {
    int i = blockIdx.x * blockDim.x + threadIdx.x;
    if (i < N_EDGES) {
        int p = atomicAdd(&g_fill[dst[i]], 1);
        g_esrc[p] = src[i];
    }
}

// ============ fused layer: gather + norms + GEMM + bias (+relu) ============
// One warp per dst node. Lane owns output cols {lane, lane+32}.
// Gather accumulates norm_out[s]*x[s] into two accumulator pairs (unroll-2)
// so the four 128B row loads per step are independent (MLP=4+), then the
// 64x64 GEMM runs via shfl broadcast against W staged in shared.
// inp == nullptr -> read g_h; outp == nullptr -> write g_h.
__global__ void __launch_bounds__(256) k_layer(const float* inp,
                                               const float* __restrict__ W,
                                               const float* __restrict__ b,
                                               float* outp, int relu) {
    const float* __restrict__ in  = inp  ? inp  : (const float*)g_h;
    float*       __restrict__ out = outp ? outp : (float*)g_h;
    __shared__ float Ws[D * D];
    for (int i = threadIdx.x; i < D * D; i += blockDim.x) Ws[i] = W[i];
    __syncthreads();

    int lane = threadIdx.x & 31;
    int warp = threadIdx.x >> 5;
    int wpb  = blockDim.x >> 5;
    float b0 = __ldg(b + lane);
    float b1 = __ldg(b + 32 + lane);

    for (int v = blockIdx.x * wpb + warp; v < N_NODES; v += gridDim.x * wpb) {
        int s0 = g_rowptr[v];
        int s1 = g_rowptr[v + 1];
        float accA0 = 0.f, accA1 = 0.f;   // even edges
        float accB0 = 0.f, accB1 = 0.f;   // odd edges
        for (int base = s0; base < s1; base += 32) {
            int idx = base + lane;
            int se = (idx < s1) ? __ldg(g_esrc + idx) : 0;
            int n = min(32, s1 - base);
            int j = 0;
            for (; j + 2 <= n; j += 2) {
                int sa = __shfl_sync(0xffffffffu, se, j);
                int sb = __shfl_sync(0xffffffffu, se, j + 1);
                float na = __ldg(g_norm_out + sa);
                float nb = __ldg(g_norm_out + sb);
                const float* ra = in + (size_t)sa * D;
                const float* rb = in + (size_t)sb * D;
                float a0 = __ldg(ra + lane);
                float a1 = __ldg(ra + 32 + lane);
                float c0 = __ldg(rb + lane);
                float c1 = __ldg(rb + 32 + lane);
                accA0 = fmaf(na, a0, accA0);
                accA1 = fmaf(na, a1, accA1);
                accB0 = fmaf(nb, c0, accB0);
                accB1 = fmaf(nb, c1, accB1);
            }
            if (j < n) {
                int sa = __shfl_sync(0xffffffffu, se, j);
                float na = __ldg(g_norm_out + sa);
                const float* ra = in + (size_t)sa * D;
                accA0 = fmaf(na, __ldg(ra + lane), accA0);
                accA1 = fmaf(na, __ldg(ra + 32 + lane), accA1);
            }
        }
        float ni = __ldg(g_norm_in + v);
        float a0 = (accA0 + accB0) * ni;
        float a1 = (accA1 + accB1) * ni;
        float o0 = b0, o1 = b1;
#pragma unroll
        for (int k = 0; k < 32; k++) {
            float ak = __shfl_sync(0xffffffffu, a0, k);
            o0 = fmaf(ak, Ws[k * D + lane], o0);
            o1 = fmaf(ak, Ws[k * D + 32 + lane], o1);
        }
#pragma unroll
        for (int k = 0; k < 32; k++) {
            float ak = __shfl_sync(0xffffffffu, a1, k);
            o0 = fmaf(ak, Ws[(k + 32) * D + lane], o0);
            o1 = fmaf(ak, Ws[(k + 32) * D + 32 + lane], o1);
        }
        if (relu) { o0 = fmaxf(o0, 0.f); o1 = fmaxf(o1, 0.f); }
        out[(size_t)v * D + lane] = o0;
        out[(size_t)v * D + 32 + lane] = o1;
    }
}

extern "C" void kernel_launch(void* const* d_in, const int* in_sizes, int n_in,
                              void* d_out, int out_size) {
    const int*   src = (const int*)d_in[0];
    const int*   dst = (const int*)d_in[1];
    const float* x   = (const float*)d_in[2];
    const float* W1  = (const float*)d_in[3];
    const float* b1  = (const float*)d_in[4];
    const float* W2  = (const float*)d_in[5];
    const float* b2  = (const float*)d_in[6];
    float* out = (float*)d_out;

    const int T = 256;
    // ---- CSR build (by dst) + norms ----
    k_zero_deg<<<(N_NODES + T - 1) / T, T>>>();
    k_hist<<<(N_EDGES + T - 1) / T, T>>>(src, dst);
    k_norms<<<(N_NODES + T - 1) / T, T>>>();
    k_scan1<<<SCAN_NB, SCAN_BS>>>();
    k_scan2<<<1, 128>>>();
    k_scan3<<<(N_NODES + T - 1) / T, T>>>();
    k_bucket<<<(N_EDGES + T - 1) / T, T>>>(src, dst);

    // ---- fused layers: one warp per node, no intermediate agg buffer ----
    const int LB = (N_NODES + 8 - 1) / 8;   // 8 warps per block, 1 node per warp
    k_layer<<<LB, T>>>(x, W1, b1, nullptr, 1);        // h = relu(gcn(x))
    k_layer<<<LB, T>>>(nullptr, W2, b2, out, 0);      // out = gcn(h)
}